// round 2
// baseline (speedup 1.0000x reference)
#include <cuda_runtime.h>

#define NN 2048
#define CC 128
#define NSPEC 10
#define DD 9
#define NM_TOT 219          // 9 (deg1) + 45 (deg2) + 165 (deg3)
#define PSTRIDE 12          // 9 outputs padded to 12 floats (48B, float4-aligned)
#define PROW (NM_TOT * PSTRIDE)   // 2628 floats per (s,c)
#define MAXGRP 74
#define CPB 4               // channels per block in main kernel

// Scratch (no cudaMalloc allowed)
__device__ float g_P[(size_t)NSPEC * CC * PROW];   // ~13.5 MB
__device__ float g_U3s[165 * 108];
__device__ float g_U2s[45 * 24];
__device__ float g_U1s[9 * 9];
__device__ int   g_list[MAXGRP * 32];
__device__ int   g_gspec[MAXGRP];

// ---------------------------------------------------------------------------
// Shared monomial ordering: m 0..8 = deg1(a); then for a<=b: deg2(a,b),
// then for j>=b: deg3(a,b,j). Must match the main kernel's unrolled loop.
// ---------------------------------------------------------------------------
__device__ __forceinline__ void decode_m(int m, int& deg, int& A, int& B, int& J, int& sidx)
{
    if (m < 9) { deg = 1; A = m; B = 0; J = 0; sidx = m; return; }
    int mm = 9, s2 = 0, s3 = 0;
    for (int a = 0; a < 9; a++) {
        for (int b = a; b < 9; b++) {
            if (mm == m) { deg = 2; A = a; B = b; J = 0; sidx = s2; return; }
            mm++; s2++;
            for (int j = b; j < 9; j++) {
                if (mm == m) { deg = 3; A = a; B = b; J = j; sidx = s3; return; }
                mm++; s3++;
            }
        }
    }
    deg = 0; A = B = J = sidx = 0;
}

// ---------------------------------------------------------------------------
// Kernel A: bucket nodes by species into 32-aligned groups (padded with -1)
// ---------------------------------------------------------------------------
__global__ void bucket_kernel(const int* __restrict__ index)
{
    __shared__ int cnt[NSPEC];
    __shared__ int cur[NSPEC];
    int t = threadIdx.x;
    if (t < NSPEC) cnt[t] = 0;
    __syncthreads();
    for (int n = t; n < NN; n += blockDim.x) atomicAdd(&cnt[index[n]], 1);
    __syncthreads();
    if (t == 0) {
        int off = 0, g = 0;
        for (int s = 0; s < NSPEC; s++) {
            cur[s] = off;
            int grp = (cnt[s] + 31) >> 5;
            for (int k = 0; k < grp; k++) g_gspec[g++] = s;
            off += grp * 32;
        }
        for (; g < MAXGRP; g++) g_gspec[g] = -1;
    }
    __syncthreads();
    for (int i = t; i < MAXGRP * 32; i += blockDim.x) g_list[i] = -1;
    __syncthreads();
    for (int n = t; n < NN; n += blockDim.x) {
        int s = index[n];
        int p = atomicAdd(&cur[s], 1);
        g_list[p] = n;
    }
}

// ---------------------------------------------------------------------------
// Kernel B0: symmetrize U tensors over permutations of the contracted D-indices
// grid = 219 blocks, 128 threads
// ---------------------------------------------------------------------------
__global__ void usym_kernel(const float* __restrict__ U3_0e, const float* __restrict__ U3_1o,
                            const float* __restrict__ U3_2e,
                            const float* __restrict__ U2_0e, const float* __restrict__ U2_1o,
                            const float* __restrict__ U2_2e,
                            const float* __restrict__ U1_0e, const float* __restrict__ U1_1o,
                            const float* __restrict__ U1_2e)
{
    int m = blockIdx.x;
    int deg, A, B, J, sidx;
    decode_m(m, deg, A, B, J, sidx);
    int t = threadIdx.x;

    if (deg == 1) {
        if (t < 9) {
            float v;
            if (t == 0)      v = U1_0e[A];
            else if (t < 4)  v = U1_1o[A * 3 + (t - 1)];
            else             v = U1_2e[A * 5 + (t - 4)];
            g_U1s[sidx * 9 + t] = v;
        }
    } else if (deg == 2) {
        if (t < 24) {
            int e = t;
            float acc = 0.f;
            int np = (A == B) ? 1 : 2;
            for (int p = 0; p < np; p++) {
                int pa = p ? B : A;
                int pb = p ? A : B;
                int base2 = pa * 9 + pb;
                float v;
                if (e < 3) {
                    v = U2_0e[base2 * 3 + e];
                } else if (e < 9) {
                    int k = (e - 3) / 3, i = (e - 3) % 3;
                    v = U2_1o[(base2 * 2 + k) * 3 + i];
                } else {
                    int k = (e - 9) / 5, i = (e - 9) % 5;
                    v = U2_2e[(base2 * 3 + k) * 5 + i];
                }
                acc += v;
            }
            g_U2s[sidx * 24 + e] = acc;
        }
    } else { // deg 3
        if (t < 108) {
            int e = t;
            int perm[6][3];
            int np;
            if (A == B && B == J) {
                np = 1;
                perm[0][0] = A; perm[0][1] = A; perm[0][2] = A;
            } else if (A == B) {
                np = 3;
                int P[3][3] = {{A, A, J}, {A, J, A}, {J, A, A}};
                for (int p = 0; p < 3; p++) for (int q = 0; q < 3; q++) perm[p][q] = P[p][q];
            } else if (B == J) {
                np = 3;
                int P[3][3] = {{A, B, B}, {B, A, B}, {B, B, A}};
                for (int p = 0; p < 3; p++) for (int q = 0; q < 3; q++) perm[p][q] = P[p][q];
            } else {
                np = 6;
                int P[6][3] = {{A, B, J}, {A, J, B}, {B, A, J}, {B, J, A}, {J, A, B}, {J, B, A}};
                for (int p = 0; p < 6; p++) for (int q = 0; q < 3; q++) perm[p][q] = P[p][q];
            }
            float acc = 0.f;
            for (int p = 0; p < np; p++) {
                int base3 = (perm[p][0] * 9 + perm[p][1]) * 9 + perm[p][2];
                float v;
                if (e < 10) {
                    v = U3_0e[base3 * 10 + e];
                } else if (e < 43) {
                    int k = (e - 10) / 3, i = (e - 10) % 3;
                    v = U3_1o[(base3 * 11 + k) * 3 + i];
                } else {
                    int k = (e - 43) / 5, i = (e - 43) % 5;
                    v = U3_2e[(base3 * 13 + k) * 5 + i];
                }
                acc += v;
            }
            g_U3s[sidx * 108 + e] = acc;
        }
    }
}

// ---------------------------------------------------------------------------
// Kernel B: contract symmetrized U with per-species weights ->
//   P[s][c][m][0..8] (stride 12). grid = (219, 10), block = 128 (c)
// ---------------------------------------------------------------------------
__global__ void pbuild_kernel(const float* __restrict__ W3_0e, const float* __restrict__ W3_1o,
                              const float* __restrict__ W3_2e,
                              const float* __restrict__ W2_0e, const float* __restrict__ W2_1o,
                              const float* __restrict__ W2_2e,
                              const float* __restrict__ W1_0e, const float* __restrict__ W1_1o,
                              const float* __restrict__ W1_2e)
{
    int m = blockIdx.x;
    int s = blockIdx.y;
    int c = threadIdx.x;
    int deg, A, B, J, sidx;
    decode_m(m, deg, A, B, J, sidx);

    float acc[9];
#pragma unroll
    for (int i = 0; i < 9; i++) acc[i] = 0.f;

    if (deg == 1) {
        const float* u = g_U1s + sidx * 9;
        float w0 = W1_0e[s * CC + c];
        float w1 = W1_1o[s * CC + c];
        float w2 = W1_2e[s * CC + c];
        acc[0] = u[0] * w0;
#pragma unroll
        for (int i = 0; i < 3; i++) acc[1 + i] = u[1 + i] * w1;
#pragma unroll
        for (int i = 0; i < 5; i++) acc[4 + i] = u[4 + i] * w2;
    } else if (deg == 2) {
        const float* u = g_U2s + sidx * 24;
#pragma unroll
        for (int k = 0; k < 3; k++) {
            float w = W2_0e[(s * 3 + k) * CC + c];
            acc[0] += u[k] * w;
        }
#pragma unroll
        for (int k = 0; k < 2; k++) {
            float w = W2_1o[(s * 2 + k) * CC + c];
#pragma unroll
            for (int i = 0; i < 3; i++) acc[1 + i] += u[3 + k * 3 + i] * w;
        }
#pragma unroll
        for (int k = 0; k < 3; k++) {
            float w = W2_2e[(s * 3 + k) * CC + c];
#pragma unroll
            for (int i = 0; i < 5; i++) acc[4 + i] += u[9 + k * 5 + i] * w;
        }
    } else {
        const float* u = g_U3s + sidx * 108;
#pragma unroll
        for (int k = 0; k < 10; k++) {
            float w = W3_0e[(s * 10 + k) * CC + c];
            acc[0] += u[k] * w;
        }
#pragma unroll
        for (int k = 0; k < 11; k++) {
            float w = W3_1o[(s * 11 + k) * CC + c];
#pragma unroll
            for (int i = 0; i < 3; i++) acc[1 + i] += u[10 + k * 3 + i] * w;
        }
#pragma unroll
        for (int k = 0; k < 13; k++) {
            float w = W3_2e[(s * 13 + k) * CC + c];
#pragma unroll
            for (int i = 0; i < 5; i++) acc[4 + i] += u[43 + k * 5 + i] * w;
        }
    }

    float* dst = g_P + ((size_t)(s * CC + c) * NM_TOT + m) * PSTRIDE;
#pragma unroll
    for (int i = 0; i < 9; i++) dst[i] = acc[i];
    dst[9] = 0.f; dst[10] = 0.f; dst[11] = 0.f;
}

// ---------------------------------------------------------------------------
// Main kernel: block = (species node-group of 32, 4 channels). Warp w handles
// channel cb+w for all 32 nodes; P reads are shared-memory broadcasts.
// grid = (74, 32), block = 128
// ---------------------------------------------------------------------------
__device__ __forceinline__ void fma9(float* o, const float* p, float m)
{
    float4 p0 = *reinterpret_cast<const float4*>(p);
    float4 p1 = *reinterpret_cast<const float4*>(p + 4);
    float  p8 = p[8];
    o[0] += p0.x * m; o[1] += p0.y * m; o[2] += p0.z * m; o[3] += p0.w * m;
    o[4] += p1.x * m; o[5] += p1.y * m; o[6] += p1.z * m; o[7] += p1.w * m;
    o[8] += p8 * m;
}

__global__ __launch_bounds__(128) void main_kernel(const float* __restrict__ nf,
                                                   float* __restrict__ out)
{
    __shared__ float sP[CPB * PROW]; // 42048 bytes

    int g = blockIdx.x;
    int s = g_gspec[g];
    if (s < 0) return;
    int cb = blockIdx.y * CPB;

    // stage P for 4 consecutive channels (contiguous in g_P)
    {
        const float4* src = reinterpret_cast<const float4*>(g_P + (size_t)(s * CC + cb) * PROW);
        float4* dst = reinterpret_cast<float4*>(sP);
        for (int i = threadIdx.x; i < CPB * PROW / 4; i += blockDim.x) dst[i] = src[i];
    }
    __syncthreads();

    int warp = threadIdx.x >> 5;
    int lane = threadIdx.x & 31;
    int c = cb + warp;
    int nd = g_list[g * 32 + lane];

    float x[9];
    if (nd >= 0) {
        const float* xp = nf + ((size_t)nd * CC + c) * DD;
#pragma unroll
        for (int i = 0; i < 9; i++) x[i] = xp[i];
    } else {
#pragma unroll
        for (int i = 0; i < 9; i++) x[i] = 0.f;
    }

    const float* sp = sP + warp * PROW;
    float o[9];
#pragma unroll
    for (int i = 0; i < 9; i++) o[i] = 0.f;

    int off = 0;
    // deg1
#pragma unroll
    for (int a = 0; a < 9; a++) {
        fma9(o, sp + off, x[a]);
        off += PSTRIDE;
    }
    // deg2 + deg3 interleaved (must match decode_m ordering)
#pragma unroll
    for (int a = 0; a < 9; a++) {
#pragma unroll
        for (int b = a; b < 9; b++) {
            float xab = x[a] * x[b];
            fma9(o, sp + off, xab);
            off += PSTRIDE;
#pragma unroll
            for (int j = b; j < 9; j++) {
                fma9(o, sp + off, xab * x[j]);
                off += PSTRIDE;
            }
        }
    }

    if (nd >= 0) {
        float* op = out + ((size_t)nd * CC + c) * DD;
#pragma unroll
        for (int i = 0; i < 9; i++) op[i] = o[i];
    }
}

// ---------------------------------------------------------------------------
extern "C" void kernel_launch(void* const* d_in, const int* in_sizes, int n_in,
                              void* d_out, int out_size)
{
    const float* nf   = (const float*)d_in[0];
    const int*   indx = (const int*)d_in[1];

    const float *U3_0e, *U3_1o, *U3_2e, *U2_0e, *U2_1o, *U2_2e, *U1_0e, *U1_1o, *U1_2e;
    const float *W3_0e, *W3_1o, *W3_2e, *W2_0e, *W2_1o, *W2_2e, *W1_0e, *W1_1o, *W1_2e;

    if (in_sizes[3] == 12800) {
        // interleaved (setup_inputs dict order): U3_0e, W3_0e, U3_1o, W3_1o, ...
        U3_0e = (const float*)d_in[2];  W3_0e = (const float*)d_in[3];
        U3_1o = (const float*)d_in[4];  W3_1o = (const float*)d_in[5];
        U3_2e = (const float*)d_in[6];  W3_2e = (const float*)d_in[7];
        U2_0e = (const float*)d_in[8];  W2_0e = (const float*)d_in[9];
        U2_1o = (const float*)d_in[10]; W2_1o = (const float*)d_in[11];
        U2_2e = (const float*)d_in[12]; W2_2e = (const float*)d_in[13];
        U1_0e = (const float*)d_in[14]; W1_0e = (const float*)d_in[15];
        U1_1o = (const float*)d_in[16]; W1_1o = (const float*)d_in[17];
        U1_2e = (const float*)d_in[18]; W1_2e = (const float*)d_in[19];
    } else {
        // grouped (reference signature order): all U's then all W's
        U3_0e = (const float*)d_in[2];  U3_1o = (const float*)d_in[3];
        U3_2e = (const float*)d_in[4];  U2_0e = (const float*)d_in[5];
        U2_1o = (const float*)d_in[6];  U2_2e = (const float*)d_in[7];
        U1_0e = (const float*)d_in[8];  U1_1o = (const float*)d_in[9];
        U1_2e = (const float*)d_in[10];
        W3_0e = (const float*)d_in[11]; W3_1o = (const float*)d_in[12];
        W3_2e = (const float*)d_in[13]; W2_0e = (const float*)d_in[14];
        W2_1o = (const float*)d_in[15]; W2_2e = (const float*)d_in[16];
        W1_0e = (const float*)d_in[17]; W1_1o = (const float*)d_in[18];
        W1_2e = (const float*)d_in[19];
    }

    bucket_kernel<<<1, 256>>>(indx);
    usym_kernel<<<NM_TOT, 128>>>(U3_0e, U3_1o, U3_2e, U2_0e, U2_1o, U2_2e, U1_0e, U1_1o, U1_2e);
    pbuild_kernel<<<dim3(NM_TOT, NSPEC), 128>>>(W3_0e, W3_1o, W3_2e, W2_0e, W2_1o, W2_2e,
                                                W1_0e, W1_1o, W1_2e);
    main_kernel<<<dim3(MAXGRP, CC / CPB), 128>>>(nf, (float*)d_out);
}

// round 3
// speedup vs baseline: 1.0225x; 1.0225x over previous
#include <cuda_runtime.h>

#define NN 2048
#define CC 128
#define NSPEC 10
#define DD 9
#define NM_TOT 219          // 9 (deg1) + 45 (deg2) + 165 (deg3)
#define PSTRIDE 12          // 9 outputs padded to 12 floats (48B, float4-aligned)
#define PROW (NM_TOT * PSTRIDE)   // 2628 floats per (s,c)
#define MAXGRP 74
#define CPB 4               // channels per block in main kernel

// Scratch (no cudaMalloc allowed)
__device__ float g_P[(size_t)NSPEC * CC * PROW];   // ~13.5 MB
__device__ float g_U3s[165 * 108];
__device__ float g_U2s[45 * 24];
__device__ float g_U1s[9 * 9];
__device__ int   g_list[MAXGRP * 32];
__device__ int   g_gspec[MAXGRP];

// ---------------------------------------------------------------------------
// Shared monomial ordering: m 0..8 = deg1(a); then for a<=b: deg2(a,b),
// then for j>=b: deg3(a,b,j). Must match the main kernel's unrolled loop.
// ---------------------------------------------------------------------------
__device__ __forceinline__ void decode_m(int m, int& deg, int& A, int& B, int& J, int& sidx)
{
    if (m < 9) { deg = 1; A = m; B = 0; J = 0; sidx = m; return; }
    int mm = 9, s2 = 0, s3 = 0;
    for (int a = 0; a < 9; a++) {
        for (int b = a; b < 9; b++) {
            if (mm == m) { deg = 2; A = a; B = b; J = 0; sidx = s2; return; }
            mm++; s2++;
            for (int j = b; j < 9; j++) {
                if (mm == m) { deg = 3; A = a; B = b; J = j; sidx = s3; return; }
                mm++; s3++;
            }
        }
    }
    deg = 0; A = B = J = sidx = 0;
}

// ---------------------------------------------------------------------------
// Kernel A: bucket nodes by species into 32-aligned groups (padded with -1)
// ---------------------------------------------------------------------------
__global__ void bucket_kernel(const int* __restrict__ index)
{
    __shared__ int cnt[NSPEC];
    __shared__ int cur[NSPEC];
    int t = threadIdx.x;
    if (t < NSPEC) cnt[t] = 0;
    __syncthreads();
    for (int n = t; n < NN; n += blockDim.x) atomicAdd(&cnt[index[n]], 1);
    __syncthreads();
    if (t == 0) {
        int off = 0, g = 0;
        for (int s = 0; s < NSPEC; s++) {
            cur[s] = off;
            int grp = (cnt[s] + 31) >> 5;
            for (int k = 0; k < grp; k++) g_gspec[g++] = s;
            off += grp * 32;
        }
        for (; g < MAXGRP; g++) g_gspec[g] = -1;
    }
    __syncthreads();
    for (int i = t; i < MAXGRP * 32; i += blockDim.x) g_list[i] = -1;
    __syncthreads();
    for (int n = t; n < NN; n += blockDim.x) {
        int s = index[n];
        int p = atomicAdd(&cur[s], 1);
        g_list[p] = n;
    }
}

// ---------------------------------------------------------------------------
// Kernel B0: symmetrize U tensors over permutations of the contracted D-indices
// grid = 219 blocks, 128 threads
// ---------------------------------------------------------------------------
__global__ void usym_kernel(const float* __restrict__ U3_0e, const float* __restrict__ U3_1o,
                            const float* __restrict__ U3_2e,
                            const float* __restrict__ U2_0e, const float* __restrict__ U2_1o,
                            const float* __restrict__ U2_2e,
                            const float* __restrict__ U1_0e, const float* __restrict__ U1_1o,
                            const float* __restrict__ U1_2e)
{
    int m = blockIdx.x;
    int deg, A, B, J, sidx;
    decode_m(m, deg, A, B, J, sidx);
    int t = threadIdx.x;

    if (deg == 1) {
        if (t < 9) {
            float v;
            if (t == 0)      v = U1_0e[A];
            else if (t < 4)  v = U1_1o[A * 3 + (t - 1)];
            else             v = U1_2e[A * 5 + (t - 4)];
            g_U1s[sidx * 9 + t] = v;
        }
    } else if (deg == 2) {
        if (t < 24) {
            int e = t;
            float acc = 0.f;
            int np = (A == B) ? 1 : 2;
            for (int p = 0; p < np; p++) {
                int pa = p ? B : A;
                int pb = p ? A : B;
                int base2 = pa * 9 + pb;
                float v;
                if (e < 3) {
                    v = U2_0e[base2 * 3 + e];
                } else if (e < 9) {
                    int k = (e - 3) / 3, i = (e - 3) % 3;
                    v = U2_1o[(base2 * 2 + k) * 3 + i];
                } else {
                    int k = (e - 9) / 5, i = (e - 9) % 5;
                    v = U2_2e[(base2 * 3 + k) * 5 + i];
                }
                acc += v;
            }
            g_U2s[sidx * 24 + e] = acc;
        }
    } else { // deg 3
        if (t < 108) {
            int e = t;
            int perm[6][3];
            int np;
            if (A == B && B == J) {
                np = 1;
                perm[0][0] = A; perm[0][1] = A; perm[0][2] = A;
            } else if (A == B) {
                np = 3;
                int P[3][3] = {{A, A, J}, {A, J, A}, {J, A, A}};
                for (int p = 0; p < 3; p++) for (int q = 0; q < 3; q++) perm[p][q] = P[p][q];
            } else if (B == J) {
                np = 3;
                int P[3][3] = {{A, B, B}, {B, A, B}, {B, B, A}};
                for (int p = 0; p < 3; p++) for (int q = 0; q < 3; q++) perm[p][q] = P[p][q];
            } else {
                np = 6;
                int P[6][3] = {{A, B, J}, {A, J, B}, {B, A, J}, {B, J, A}, {J, A, B}, {J, B, A}};
                for (int p = 0; p < 6; p++) for (int q = 0; q < 3; q++) perm[p][q] = P[p][q];
            }
            float acc = 0.f;
            for (int p = 0; p < np; p++) {
                int base3 = (perm[p][0] * 9 + perm[p][1]) * 9 + perm[p][2];
                float v;
                if (e < 10) {
                    v = U3_0e[base3 * 10 + e];
                } else if (e < 43) {
                    int k = (e - 10) / 3, i = (e - 10) % 3;
                    v = U3_1o[(base3 * 11 + k) * 3 + i];
                } else {
                    int k = (e - 43) / 5, i = (e - 43) % 5;
                    v = U3_2e[(base3 * 13 + k) * 5 + i];
                }
                acc += v;
            }
            g_U3s[sidx * 108 + e] = acc;
        }
    }
}

// ---------------------------------------------------------------------------
// Kernel B: contract symmetrized U with per-species weights ->
//   P[s][c][m][0..8] (stride 12). grid = (219, 10), block = 128 (c)
// ---------------------------------------------------------------------------
__global__ void pbuild_kernel(const float* __restrict__ W3_0e, const float* __restrict__ W3_1o,
                              const float* __restrict__ W3_2e,
                              const float* __restrict__ W2_0e, const float* __restrict__ W2_1o,
                              const float* __restrict__ W2_2e,
                              const float* __restrict__ W1_0e, const float* __restrict__ W1_1o,
                              const float* __restrict__ W1_2e)
{
    int m = blockIdx.x;
    int s = blockIdx.y;
    int c = threadIdx.x;
    int deg, A, B, J, sidx;
    decode_m(m, deg, A, B, J, sidx);

    float acc[9];
#pragma unroll
    for (int i = 0; i < 9; i++) acc[i] = 0.f;

    if (deg == 1) {
        const float* u = g_U1s + sidx * 9;
        float w0 = W1_0e[s * CC + c];
        float w1 = W1_1o[s * CC + c];
        float w2 = W1_2e[s * CC + c];
        acc[0] = u[0] * w0;
#pragma unroll
        for (int i = 0; i < 3; i++) acc[1 + i] = u[1 + i] * w1;
#pragma unroll
        for (int i = 0; i < 5; i++) acc[4 + i] = u[4 + i] * w2;
    } else if (deg == 2) {
        const float* u = g_U2s + sidx * 24;
#pragma unroll
        for (int k = 0; k < 3; k++) {
            float w = W2_0e[(s * 3 + k) * CC + c];
            acc[0] += u[k] * w;
        }
#pragma unroll
        for (int k = 0; k < 2; k++) {
            float w = W2_1o[(s * 2 + k) * CC + c];
#pragma unroll
            for (int i = 0; i < 3; i++) acc[1 + i] += u[3 + k * 3 + i] * w;
        }
#pragma unroll
        for (int k = 0; k < 3; k++) {
            float w = W2_2e[(s * 3 + k) * CC + c];
#pragma unroll
            for (int i = 0; i < 5; i++) acc[4 + i] += u[9 + k * 5 + i] * w;
        }
    } else {
        const float* u = g_U3s + sidx * 108;
#pragma unroll
        for (int k = 0; k < 10; k++) {
            float w = W3_0e[(s * 10 + k) * CC + c];
            acc[0] += u[k] * w;
        }
#pragma unroll
        for (int k = 0; k < 11; k++) {
            float w = W3_1o[(s * 11 + k) * CC + c];
#pragma unroll
            for (int i = 0; i < 3; i++) acc[1 + i] += u[10 + k * 3 + i] * w;
        }
#pragma unroll
        for (int k = 0; k < 13; k++) {
            float w = W3_2e[(s * 13 + k) * CC + c];
#pragma unroll
            for (int i = 0; i < 5; i++) acc[4 + i] += u[43 + k * 5 + i] * w;
        }
    }

    float* dst = g_P + ((size_t)(s * CC + c) * NM_TOT + m) * PSTRIDE;
#pragma unroll
    for (int i = 0; i < 9; i++) dst[i] = acc[i];
    dst[9] = 0.f; dst[10] = 0.f; dst[11] = 0.f;
}

// ---------------------------------------------------------------------------
// Main kernel: block = (species node-group of 32, 4 channels). Warp w handles
// channel cb+w for all 32 nodes; P reads are shared-memory broadcasts.
// grid = (74, 32), block = 128
// ---------------------------------------------------------------------------
__device__ __forceinline__ void fma9(float* o, const float* p, float m)
{
    float4 p0 = *reinterpret_cast<const float4*>(p);
    float4 p1 = *reinterpret_cast<const float4*>(p + 4);
    float  p8 = p[8];
    o[0] += p0.x * m; o[1] += p0.y * m; o[2] += p0.z * m; o[3] += p0.w * m;
    o[4] += p1.x * m; o[5] += p1.y * m; o[6] += p1.z * m; o[7] += p1.w * m;
    o[8] += p8 * m;
}

__global__ __launch_bounds__(128) void main_kernel(const float* __restrict__ nf,
                                                   float* __restrict__ out)
{
    __shared__ float sP[CPB * PROW]; // 42048 bytes

    int g = blockIdx.x;
    int s = g_gspec[g];
    if (s < 0) return;
    int cb = blockIdx.y * CPB;

    // stage P for 4 consecutive channels (contiguous in g_P)
    {
        const float4* src = reinterpret_cast<const float4*>(g_P + (size_t)(s * CC + cb) * PROW);
        float4* dst = reinterpret_cast<float4*>(sP);
        for (int i = threadIdx.x; i < CPB * PROW / 4; i += blockDim.x) dst[i] = src[i];
    }
    __syncthreads();

    int warp = threadIdx.x >> 5;
    int lane = threadIdx.x & 31;
    int c = cb + warp;
    int nd = g_list[g * 32 + lane];

    float x[9];
    if (nd >= 0) {
        const float* xp = nf + ((size_t)nd * CC + c) * DD;
#pragma unroll
        for (int i = 0; i < 9; i++) x[i] = xp[i];
    } else {
#pragma unroll
        for (int i = 0; i < 9; i++) x[i] = 0.f;
    }

    const float* sp = sP + warp * PROW;
    float o[9];
#pragma unroll
    for (int i = 0; i < 9; i++) o[i] = 0.f;

    int off = 0;
    // deg1
#pragma unroll
    for (int a = 0; a < 9; a++) {
        fma9(o, sp + off, x[a]);
        off += PSTRIDE;
    }
    // deg2 + deg3 interleaved (must match decode_m ordering)
#pragma unroll
    for (int a = 0; a < 9; a++) {
#pragma unroll
        for (int b = a; b < 9; b++) {
            float xab = x[a] * x[b];
            fma9(o, sp + off, xab);
            off += PSTRIDE;
#pragma unroll
            for (int j = b; j < 9; j++) {
                fma9(o, sp + off, xab * x[j]);
                off += PSTRIDE;
            }
        }
    }

    if (nd >= 0) {
        float* op = out + ((size_t)nd * CC + c) * DD;
#pragma unroll
        for (int i = 0; i < 9; i++) op[i] = o[i];
    }
}

// ---------------------------------------------------------------------------
extern "C" void kernel_launch(void* const* d_in, const int* in_sizes, int n_in,
                              void* d_out, int out_size)
{
    const float* nf   = (const float*)d_in[0];
    const int*   indx = (const int*)d_in[1];

    const float *U3_0e, *U3_1o, *U3_2e, *U2_0e, *U2_1o, *U2_2e, *U1_0e, *U1_1o, *U1_2e;
    const float *W3_0e, *W3_1o, *W3_2e, *W2_0e, *W2_1o, *W2_2e, *W1_0e, *W1_1o, *W1_2e;

    if (in_sizes[3] == 12800) {
        // interleaved (setup_inputs dict order): U3_0e, W3_0e, U3_1o, W3_1o, ...
        U3_0e = (const float*)d_in[2];  W3_0e = (const float*)d_in[3];
        U3_1o = (const float*)d_in[4];  W3_1o = (const float*)d_in[5];
        U3_2e = (const float*)d_in[6];  W3_2e = (const float*)d_in[7];
        U2_0e = (const float*)d_in[8];  W2_0e = (const float*)d_in[9];
        U2_1o = (const float*)d_in[10]; W2_1o = (const float*)d_in[11];
        U2_2e = (const float*)d_in[12]; W2_2e = (const float*)d_in[13];
        U1_0e = (const float*)d_in[14]; W1_0e = (const float*)d_in[15];
        U1_1o = (const float*)d_in[16]; W1_1o = (const float*)d_in[17];
        U1_2e = (const float*)d_in[18]; W1_2e = (const float*)d_in[19];
    } else {
        // grouped (reference signature order): all U's then all W's
        U3_0e = (const float*)d_in[2];  U3_1o = (const float*)d_in[3];
        U3_2e = (const float*)d_in[4];  U2_0e = (const float*)d_in[5];
        U2_1o = (const float*)d_in[6];  U2_2e = (const float*)d_in[7];
        U1_0e = (const float*)d_in[8];  U1_1o = (const float*)d_in[9];
        U1_2e = (const float*)d_in[10];
        W3_0e = (const float*)d_in[11]; W3_1o = (const float*)d_in[12];
        W3_2e = (const float*)d_in[13]; W2_0e = (const float*)d_in[14];
        W2_1o = (const float*)d_in[15]; W2_2e = (const float*)d_in[16];
        W1_0e = (const float*)d_in[17]; W1_1o = (const float*)d_in[18];
        W1_2e = (const float*)d_in[19];
    }

    bucket_kernel<<<1, 256>>>(indx);
    usym_kernel<<<NM_TOT, 128>>>(U3_0e, U3_1o, U3_2e, U2_0e, U2_1o, U2_2e, U1_0e, U1_1o, U1_2e);
    pbuild_kernel<<<dim3(NM_TOT, NSPEC), 128>>>(W3_0e, W3_1o, W3_2e, W2_0e, W2_1o, W2_2e,
                                                W1_0e, W1_1o, W1_2e);
    main_kernel<<<dim3(MAXGRP, CC / CPB), 128>>>(nf, (float*)d_out);
}